// round 3
// baseline (speedup 1.0000x reference)
#include <cuda_runtime.h>
#include <cstdint>

// Problem constants (fixed by the dataset)
#define N_NODES 50000
#define E_EDGES 1600000
#define IN_DIM  256
#define HID     512
#define OUT_DIM 256

// -------- scratch (module-static; no runtime allocation) --------
__device__ __align__(16) float g_deg[N_NODES];            // degree (init 1.0 = self loop)
__device__ __align__(16) float g_dinv[N_NODES];           // deg^-1/2
__device__ __align__(16) float g_t[N_NODES];              // t_v = dinv[v] + sum_{u->v} dinv[u]
__device__ __align__(16) float g_ax[(size_t)N_NODES * IN_DIM];  // aggregation acc; reused as q in layer 2
__device__ __align__(16) float g_h2[(size_t)N_NODES * HID];     // sigmoid(layer1)
__device__ __align__(16) float g_Wc[IN_DIM * HID];        // W_ae @ W1
__device__ __align__(16) float g_bb[HID];                 // b_ae @ W1
__device__ int g_is64;                                    // edge_index dtype flag

// -------- helpers --------
__device__ __forceinline__ void red_add4(float* p, float4 v) {
    asm volatile("red.global.add.v4.f32 [%0], {%1,%2,%3,%4};"
                 :: "l"(p), "f"(v.x), "f"(v.y), "f"(v.z), "f"(v.w)
                 : "memory");
}

__device__ __forceinline__ float sigmoidf(float z) {
    return 1.0f / (1.0f + __expf(-z));
}

// Read edge endpoint `which` (0=src row, 1=dst row) of edge e, dtype-agnostic.
__device__ __forceinline__ int edge_at(const void* ei, int which, int e) {
    if (g_is64) {
        return (int)((const long long*)ei)[(size_t)which * E_EDGES + e];
    } else {
        return ((const int*)ei)[(size_t)which * E_EDGES + e];
    }
}

// -------- dtype detection --------
// If edge_index is int64 (LE), every odd 32-bit word (high half) is 0 since all
// indices < 50000. If int32, odd positions hold random indices (~never all zero).
__global__ void k_detect(const int* __restrict__ ei32) {
    if (threadIdx.x == 0 && blockIdx.x == 0) {
        int is64 = 1;
        for (int i = 0; i < 1024; i++) {
            if (ei32[2 * i + 1] != 0) { is64 = 0; break; }
        }
        g_is64 = is64;
    }
}

// -------- tiny prep kernels --------
__global__ void k_init_deg() {
    int i = blockIdx.x * blockDim.x + threadIdx.x;
    if (i < N_NODES) g_deg[i] = 1.0f;   // self loop
}

__global__ void k_count(const void* __restrict__ ei) {
    int e = blockIdx.x * blockDim.x + threadIdx.x;
    if (e < E_EDGES) atomicAdd(&g_deg[edge_at(ei, 1, e)], 1.0f);
}

__global__ void k_dinv() {
    int i = blockIdx.x * blockDim.x + threadIdx.x;
    if (i < N_NODES) {
        float d = g_deg[i];
        float v = (d > 0.0f) ? rsqrtf(d) : 0.0f;
        g_dinv[i] = v;
        g_t[i] = v;     // self-loop contribution to rowsum accumulator
    }
}

// g_ax[v] := dinv[v] * x[v]   (self-loop init of the aggregation accumulator)
__global__ void k_init_ax(const float* __restrict__ x) {
    int idx = blockIdx.x * blockDim.x + threadIdx.x;    // over N*64 float4
    if (idx < N_NODES * (IN_DIM / 4)) {
        int row = idx >> 6;     // /64
        float d = g_dinv[row];
        float4 v = ((const float4*)x)[idx];
        v.x *= d; v.y *= d; v.z *= d; v.w *= d;
        ((float4*)g_ax)[idx] = v;
    }
}

// -------- scatter 1: g_ax[dst] += dinv[src] * x[src], g_t[dst] += dinv[src] --------
// one warp per edge; 256-dim rows, each lane handles 2 float4
__global__ void k_scatter1(const void* __restrict__ ei,
                           const float* __restrict__ x) {
    int e = blockIdx.x * (blockDim.x >> 5) + (threadIdx.x >> 5);
    if (e >= E_EDGES) return;
    int lane = threadIdx.x & 31;
    int src = edge_at(ei, 0, e);
    int dst = edge_at(ei, 1, e);
    float w = g_dinv[src];
    if (lane == 0) atomicAdd(&g_t[dst], w);
    const float4* xs = (const float4*)(x + (size_t)src * IN_DIM);
    float* ax = g_ax + (size_t)dst * IN_DIM;
    float4 v0 = xs[lane];
    float4 v1 = xs[lane + 32];
    v0.x *= w; v0.y *= w; v0.z *= w; v0.w *= w;
    v1.x *= w; v1.y *= w; v1.z *= w; v1.w *= w;
    red_add4(ax + lane * 4, v0);
    red_add4(ax + (lane + 32) * 4, v1);
}

// -------- W_c = W_ae @ W1  (256x512x512) --------
__global__ void k_wc(const float* __restrict__ W_ae, const float* __restrict__ W1) {
    __shared__ float wa[HID];
    int k = blockIdx.y;                                  // 0..255
    int j = blockIdx.x * 256 + threadIdx.x;              // 0..511
    for (int m = threadIdx.x; m < HID; m += 256) wa[m] = W_ae[k * HID + m];
    __syncthreads();
    float acc = 0.0f;
    #pragma unroll 8
    for (int m = 0; m < HID; m++) acc = fmaf(wa[m], W1[m * HID + j], acc);
    g_Wc[k * HID + j] = acc;
}

// g_bb = b_ae @ W1
__global__ void k_bb(const float* __restrict__ b_ae, const float* __restrict__ W1) {
    int j = blockIdx.x * 256 + threadIdx.x;
    if (j < HID) {
        float acc = 0.0f;
        for (int m = 0; m < HID; m++) acc = fmaf(b_ae[m], W1[m * HID + j], acc);
        g_bb[j] = acc;
    }
}

// -------- GEMM1: h2 = sigmoid( (dinv .* g_ax) @ Wc + s*bb + b1 ) --------
// M=50000, K=256, Ncols=512. Tiled 64x64, BK=16, 256 threads, 4x4 per thread.
// Smem rows padded to 68 floats (272B = 17*16B): avoids bank conflicts on the
// transposed As writes while keeping float4 alignment.
__global__ __launch_bounds__(256) void k_gemm1(const float* __restrict__ b1) {
    __shared__ float As[16][68];
    __shared__ float Bs[16][68];
    int tid = threadIdx.x;
    int row0 = blockIdx.x * 64;
    int col0 = blockIdx.y * 64;
    int ar = tid >> 2, ak = (tid & 3) << 2;      // A load: row-in-tile, k-in-tile
    int bk = tid >> 4, bn = (tid & 15) << 2;     // B load
    int ty = tid >> 4, tx = tid & 15;            // compute 4x4 at (ty*4, tx*4)

    float acc[4][4];
    #pragma unroll
    for (int i = 0; i < 4; i++)
        #pragma unroll
        for (int j = 0; j < 4; j++) acc[i][j] = 0.0f;

    int grow = row0 + ar;
    bool aval = grow < N_NODES;
    float da = aval ? g_dinv[grow] : 0.0f;
    const float* Arow = g_ax + (size_t)grow * IN_DIM;

    for (int k0 = 0; k0 < IN_DIM; k0 += 16) {
        float4 av = make_float4(0.f, 0.f, 0.f, 0.f);
        if (aval) av = *(const float4*)(Arow + k0 + ak);
        As[ak + 0][ar] = av.x * da;
        As[ak + 1][ar] = av.y * da;
        As[ak + 2][ar] = av.z * da;
        As[ak + 3][ar] = av.w * da;
        *(float4*)&Bs[bk][bn] = *(const float4*)&g_Wc[(k0 + bk) * HID + col0 + bn];
        __syncthreads();
        #pragma unroll
        for (int k = 0; k < 16; k++) {
            float a[4], b[4];
            #pragma unroll
            for (int i = 0; i < 4; i++) a[i] = As[k][ty * 4 + i];
            #pragma unroll
            for (int j = 0; j < 4; j++) b[j] = Bs[k][tx * 4 + j];
            #pragma unroll
            for (int i = 0; i < 4; i++)
                #pragma unroll
                for (int j = 0; j < 4; j++) acc[i][j] = fmaf(a[i], b[j], acc[i][j]);
        }
        __syncthreads();
    }
    #pragma unroll
    for (int i = 0; i < 4; i++) {
        int row = row0 + ty * 4 + i;
        if (row < N_NODES) {
            float s = g_dinv[row] * g_t[row];
            #pragma unroll
            for (int j = 0; j < 4; j++) {
                int col = col0 + tx * 4 + j;
                float z = acc[i][j] + s * g_bb[col] + b1[col];
                g_h2[(size_t)row * HID + col] = sigmoidf(z);
            }
        }
    }
}

// -------- GEMM2: q = dinv .* (h2 @ W2); writes q to g_ax (reuse) and out (self-loop init) --------
// M=50000, K=512, Ncols=256.
__global__ __launch_bounds__(256) void k_gemm2(const float* __restrict__ W2,
                                               float* __restrict__ out) {
    __shared__ float As[16][68];
    __shared__ float Bs[16][68];
    int tid = threadIdx.x;
    int row0 = blockIdx.x * 64;
    int col0 = blockIdx.y * 64;
    int ar = tid >> 2, ak = (tid & 3) << 2;
    int bk = tid >> 4, bn = (tid & 15) << 2;
    int ty = tid >> 4, tx = tid & 15;

    float acc[4][4];
    #pragma unroll
    for (int i = 0; i < 4; i++)
        #pragma unroll
        for (int j = 0; j < 4; j++) acc[i][j] = 0.0f;

    int grow = row0 + ar;
    bool aval = grow < N_NODES;
    const float* Arow = g_h2 + (size_t)grow * HID;

    for (int k0 = 0; k0 < HID; k0 += 16) {
        float4 av = make_float4(0.f, 0.f, 0.f, 0.f);
        if (aval) av = *(const float4*)(Arow + k0 + ak);
        As[ak + 0][ar] = av.x;
        As[ak + 1][ar] = av.y;
        As[ak + 2][ar] = av.z;
        As[ak + 3][ar] = av.w;
        *(float4*)&Bs[bk][bn] = *(const float4*)&W2[(k0 + bk) * OUT_DIM + col0 + bn];
        __syncthreads();
        #pragma unroll
        for (int k = 0; k < 16; k++) {
            float a[4], b[4];
            #pragma unroll
            for (int i = 0; i < 4; i++) a[i] = As[k][ty * 4 + i];
            #pragma unroll
            for (int j = 0; j < 4; j++) b[j] = Bs[k][tx * 4 + j];
            #pragma unroll
            for (int i = 0; i < 4; i++)
                #pragma unroll
                for (int j = 0; j < 4; j++) acc[i][j] = fmaf(a[i], b[j], acc[i][j]);
        }
        __syncthreads();
    }
    #pragma unroll
    for (int i = 0; i < 4; i++) {
        int row = row0 + ty * 4 + i;
        if (row < N_NODES) {
            float d = g_dinv[row];
            #pragma unroll
            for (int j = 0; j < 4; j++) {
                int col = col0 + tx * 4 + j;
                float q = d * acc[i][j];
                g_ax[(size_t)row * OUT_DIM + col] = q;   // q buffer (reuse)
                out[(size_t)row * OUT_DIM + col] = q;    // self-loop init of out accumulator
            }
        }
    }
}

// -------- scatter 2: out[dst] += q[src] (256-dim) --------
__global__ void k_scatter2(const void* __restrict__ ei,
                           float* __restrict__ out) {
    int e = blockIdx.x * (blockDim.x >> 5) + (threadIdx.x >> 5);
    if (e >= E_EDGES) return;
    int lane = threadIdx.x & 31;
    int src = edge_at(ei, 0, e);
    int dst = edge_at(ei, 1, e);
    const float4* qs = (const float4*)(g_ax + (size_t)src * OUT_DIM);
    float* op = out + (size_t)dst * OUT_DIM;
    float4 v0 = qs[lane];
    float4 v1 = qs[lane + 32];
    red_add4(op + lane * 4, v0);
    red_add4(op + (lane + 32) * 4, v1);
}

// -------- final: out = sigmoid(dinv[v] * acc + b2) --------
__global__ void k_final(const float* __restrict__ b2, float* __restrict__ out) {
    int idx = blockIdx.x * blockDim.x + threadIdx.x;    // over N*64 float4
    if (idx < N_NODES * (OUT_DIM / 4)) {
        int row = idx >> 6;
        float d = g_dinv[row];
        float4 v = ((float4*)out)[idx];
        float4 bv = ((const float4*)b2)[idx & 63];
        v.x = sigmoidf(d * v.x + bv.x);
        v.y = sigmoidf(d * v.y + bv.y);
        v.z = sigmoidf(d * v.z + bv.z);
        v.w = sigmoidf(d * v.w + bv.w);
        ((float4*)out)[idx] = v;
    }
}

// -------- launch --------
extern "C" void kernel_launch(void* const* d_in, const int* in_sizes, int n_in,
                              void* d_out, int out_size) {
    const float* x    = (const float*)d_in[0];
    const void*  ei   = d_in[1];
    const float* W_ae = (const float*)d_in[2];
    const float* b_ae = (const float*)d_in[3];
    const float* W1   = (const float*)d_in[4];
    const float* b1   = (const float*)d_in[5];
    const float* W2   = (const float*)d_in[6];
    const float* b2   = (const float*)d_in[7];
    float* out = (float*)d_out;

    k_detect<<<1, 32>>>((const int*)ei);
    k_init_deg<<<(N_NODES + 255) / 256, 256>>>();
    k_count<<<(E_EDGES + 255) / 256, 256>>>(ei);
    k_dinv<<<(N_NODES + 255) / 256, 256>>>();
    k_init_ax<<<(N_NODES * (IN_DIM / 4) + 255) / 256, 256>>>(x);
    k_scatter1<<<(E_EDGES + 7) / 8, 256>>>(ei, x);
    k_wc<<<dim3(2, 256), 256>>>(W_ae, W1);
    k_bb<<<2, 256>>>(b_ae, W1);
    k_gemm1<<<dim3((N_NODES + 63) / 64, HID / 64), 256>>>(b1);
    k_gemm2<<<dim3((N_NODES + 63) / 64, OUT_DIM / 64), 256>>>(W2, out);
    k_scatter2<<<(E_EDGES + 7) / 8, 256>>>(ei, out);
    k_final<<<(N_NODES * (OUT_DIM / 4) + 255) / 256, 256>>>(b2, out);
}

// round 13
// speedup vs baseline: 1.1443x; 1.1443x over previous
#include <cuda_runtime.h>
#include <cstdint>

// Problem constants (fixed by the dataset)
#define N_NODES 50000
#define E_EDGES 1600000
#define IN_DIM  256
#define HID     512
#define OUT_DIM 256

// ---- GEMM tiling: 128x64 block, 8 warps, warp tile 32x32, K-chunk 32 fp32 ----
#define ASTRIDE 36   // smem row stride in floats (32 + 4 pad); 144B, 16B-aligned

// -------- scratch (module-static; no runtime allocation) --------
__device__ __align__(16) float g_deg[N_NODES];
__device__ __align__(16) float g_dinv[N_NODES];
__device__ __align__(16) float g_t[N_NODES];
__device__ __align__(16) float g_ax[(size_t)N_NODES * IN_DIM];   // agg acc; reused as q after GEMM2
__device__ __align__(16) float g_h2[(size_t)N_NODES * HID];      // sigmoid(layer1), fp32
__device__ __align__(16) float g_WcT[(size_t)HID * IN_DIM];      // (W_ae@W1)^T [512][256]
__device__ __align__(16) float g_W2T[(size_t)OUT_DIM * HID];     // W2^T [256][512]
__device__ __align__(16) float g_bb[HID];                        // b_ae @ W1
__device__ int g_is64;

// -------- helpers --------
__device__ __forceinline__ void red_add4(float* p, float4 v) {
    asm volatile("red.global.add.v4.f32 [%0], {%1,%2,%3,%4};"
                 :: "l"(p), "f"(v.x), "f"(v.y), "f"(v.z), "f"(v.w) : "memory");
}
__device__ __forceinline__ float sigmoidf(float z) { return 1.0f / (1.0f + __expf(-z)); }

// fp32 -> tf32 hi/lo split: hi = rna(v); lo = rna(v - hi). hi bits are a valid fp32.
#define CVT2(H, L, V) do { \
    asm("cvt.rna.tf32.f32 %0, %1;" : "=r"(H) : "f"(V)); \
    float r_ = (V) - __uint_as_float(H); \
    asm("cvt.rna.tf32.f32 %0, %1;" : "=r"(L) : "f"(r_)); } while (0)

// m16n8k8 tf32 MMA on a named float4 accumulator (scalar operands only).
#define MMAT(C, A0, A1, A2, A3, B0, B1) \
    asm volatile("mma.sync.aligned.m16n8k8.row.col.f32.tf32.tf32.f32 " \
        "{%0,%1,%2,%3}, {%4,%5,%6,%7}, {%8,%9}, {%0,%1,%2,%3};" \
        : "+f"((C).x), "+f"((C).y), "+f"((C).z), "+f"((C).w) \
        : "r"(A0), "r"(A1), "r"(A2), "r"(A3), "r"(B0), "r"(B1))

// Per-ks B fragment setup (8 loads, 16 cvts) then one DO_MT per m-subtile.
#define DO_MT(C0, C1, C2, C3, ROFF) do { \
    float va0_ = As[rA0 + (ROFF)][kq],     va1_ = As[rA0 + (ROFF) + 8][kq]; \
    float va2_ = As[rA0 + (ROFF)][kq4],    va3_ = As[rA0 + (ROFF) + 8][kq4]; \
    uint32_t ah0_, al0_, ah1_, al1_, ah2_, al2_, ah3_, al3_; \
    CVT2(ah0_, al0_, va0_); CVT2(ah1_, al1_, va1_); \
    CVT2(ah2_, al2_, va2_); CVT2(ah3_, al3_, va3_); \
    MMAT(C0, ah0_, ah1_, ah2_, ah3_, bh00, bh01); \
    MMAT(C0, ah0_, ah1_, ah2_, ah3_, bl00, bl01); \
    MMAT(C0, al0_, al1_, al2_, al3_, bh00, bh01); \
    MMAT(C1, ah0_, ah1_, ah2_, ah3_, bh10, bh11); \
    MMAT(C1, ah0_, ah1_, ah2_, ah3_, bl10, bl11); \
    MMAT(C1, al0_, al1_, al2_, al3_, bh10, bh11); \
    MMAT(C2, ah0_, ah1_, ah2_, ah3_, bh20, bh21); \
    MMAT(C2, ah0_, ah1_, ah2_, ah3_, bl20, bl21); \
    MMAT(C2, al0_, al1_, al2_, al3_, bh20, bh21); \
    MMAT(C3, ah0_, ah1_, ah2_, ah3_, bh30, bh31); \
    MMAT(C3, ah0_, ah1_, ah2_, ah3_, bl30, bl31); \
    MMAT(C3, al0_, al1_, al2_, al3_, bh30, bh31); } while (0)

#define KSTEP() do { \
    const int kq  = ks * 8 + lq; \
    const int kq4 = kq + 4; \
    uint32_t bh00, bl00, bh01, bl01, bh10, bl10, bh11, bl11; \
    uint32_t bh20, bl20, bh21, bl21, bh30, bl30, bh31, bl31; \
    { float v_; \
      v_ = Bs[rB0][kq];      CVT2(bh00, bl00, v_); \
      v_ = Bs[rB0][kq4];     CVT2(bh01, bl01, v_); \
      v_ = Bs[rB0 + 8][kq];  CVT2(bh10, bl10, v_); \
      v_ = Bs[rB0 + 8][kq4]; CVT2(bh11, bl11, v_); \
      v_ = Bs[rB0 + 16][kq]; CVT2(bh20, bl20, v_); \
      v_ = Bs[rB0 + 16][kq4];CVT2(bh21, bl21, v_); \
      v_ = Bs[rB0 + 24][kq]; CVT2(bh30, bl30, v_); \
      v_ = Bs[rB0 + 24][kq4];CVT2(bh31, bl31, v_); } \
    DO_MT(c00, c01, c02, c03, 0); \
    DO_MT(c10, c11, c12, c13, 16); } while (0)

// Read edge endpoint `which` (0=src, 1=dst) of edge e, dtype-agnostic.
__device__ __forceinline__ int edge_at(const void* ei, int which, int e) {
    if (g_is64) return (int)((const long long*)ei)[(size_t)which * E_EDGES + e];
    return ((const int*)ei)[(size_t)which * E_EDGES + e];
}

// -------- dtype detection --------
__global__ void k_detect(const int* __restrict__ ei32) {
    if (blockIdx.x == 0) {
        int is64 = 1;
        for (int i = 0; i < 1024; i++)
            if (ei32[2 * i + 1] != 0) { is64 = 0; break; }
        if (threadIdx.x == 0) g_is64 = is64;
    }
}

// -------- prep kernels --------
__global__ void k_init_deg() {
    int i = blockIdx.x * blockDim.x + threadIdx.x;
    if (i < N_NODES) g_deg[i] = 1.0f;
}
__global__ void k_count(const void* __restrict__ ei) {
    int e = blockIdx.x * blockDim.x + threadIdx.x;
    if (e < E_EDGES) atomicAdd(&g_deg[edge_at(ei, 1, e)], 1.0f);
}
__global__ void k_dinv() {
    int i = blockIdx.x * blockDim.x + threadIdx.x;
    if (i < N_NODES) {
        float d = g_deg[i];
        float v = (d > 0.0f) ? rsqrtf(d) : 0.0f;
        g_dinv[i] = v;
        g_t[i] = v;
    }
}
__global__ void k_init_ax(const float* __restrict__ x) {
    int idx = blockIdx.x * blockDim.x + threadIdx.x;
    if (idx < N_NODES * (IN_DIM / 4)) {
        int row = idx >> 6;
        float d = g_dinv[row];
        float4 v = ((const float4*)x)[idx];
        v.x *= d; v.y *= d; v.z *= d; v.w *= d;
        ((float4*)g_ax)[idx] = v;
    }
}

// -------- scatter 1: g_ax[dst] += dinv[src]*x[src]; g_t[dst] += dinv[src] --------
__global__ void k_scatter1(const void* __restrict__ ei, const float* __restrict__ x) {
    int e = blockIdx.x * (blockDim.x >> 5) + (threadIdx.x >> 5);
    if (e >= E_EDGES) return;
    int lane = threadIdx.x & 31;
    int src = edge_at(ei, 0, e);
    int dst = edge_at(ei, 1, e);
    float w = g_dinv[src];
    if (lane == 0) atomicAdd(&g_t[dst], w);
    const float4* xs = (const float4*)(x + (size_t)src * IN_DIM);
    float* ax = g_ax + (size_t)dst * IN_DIM;
    float4 v0 = xs[lane];
    float4 v1 = xs[lane + 32];
    v0.x *= w; v0.y *= w; v0.z *= w; v0.w *= w;
    v1.x *= w; v1.y *= w; v1.z *= w; v1.w *= w;
    red_add4(ax + lane * 4, v0);
    red_add4(ax + (lane + 32) * 4, v1);
}

// -------- weight prep (fp32) --------
// WcT[j][k] = (W_ae @ W1)[k][j]
__global__ void k_wc(const float* __restrict__ W_ae, const float* __restrict__ W1) {
    __shared__ float wa[HID];
    int k = blockIdx.y;                       // 0..255
    int j = blockIdx.x * 256 + threadIdx.x;   // 0..511
    for (int m = threadIdx.x; m < HID; m += 256) wa[m] = W_ae[k * HID + m];
    __syncthreads();
    float acc = 0.0f;
    #pragma unroll 8
    for (int m = 0; m < HID; m++) acc = fmaf(wa[m], W1[m * HID + j], acc);
    g_WcT[(size_t)j * IN_DIM + k] = acc;
}
__global__ void k_bb(const float* __restrict__ b_ae, const float* __restrict__ W1) {
    int j = blockIdx.x * 256 + threadIdx.x;
    if (j < HID) {
        float acc = 0.0f;
        for (int m = 0; m < HID; m++) acc = fmaf(b_ae[m], W1[m * HID + j], acc);
        g_bb[j] = acc;
    }
}
// W2T[j][k] = W2[k][j]
__global__ void k_wt2(const float* __restrict__ W2) {
    int idx = blockIdx.x * 256 + threadIdx.x;   // < 512*256
    int kk = idx >> 8;      // 0..511
    int j  = idx & 255;     // 0..255
    g_W2T[(size_t)j * HID + kk] = W2[kk * OUT_DIM + j];
}

// -------- epilogue helpers --------
__device__ __forceinline__ void ep1(float vx, float vy, int r, int col,
                                    const float* __restrict__ bias) {
    if (r < N_NODES) {
        float s1 = g_dinv[r] * g_t[r];
        float2 o = make_float2(sigmoidf(vx + s1 * g_bb[col] + bias[col]),
                               sigmoidf(vy + s1 * g_bb[col + 1] + bias[col + 1]));
        *(float2*)(g_h2 + (size_t)r * HID + col) = o;
    }
}
__device__ __forceinline__ void ep2(float vx, float vy, int r, int col,
                                    float* __restrict__ out) {
    if (r < N_NODES) {
        float dv = g_dinv[r];
        float2 q = make_float2(dv * vx, dv * vy);
        size_t o = (size_t)r * OUT_DIM + col;
        *(float2*)(g_ax + o) = q;
        *(float2*)(out + o) = q;
    }
}

#define EPIW(EP, C, RO, CO, LAST) do { \
    EP((C).x, (C).y, rbase + (RO), cbase + (CO), LAST); \
    EP((C).z, (C).w, rbase + (RO) + 8, cbase + (CO), LAST); } while (0)

// -------- GEMM1: g_h2 = sigmoid(dinv.*(g_ax) @ WcT^T + s*bb + b1)  [K=256] --------
__global__ __launch_bounds__(256) void k_gemm1(const float* __restrict__ bias) {
    __shared__ float As[128][ASTRIDE];
    __shared__ float Bs[64][ASTRIDE];
    const int tid = threadIdx.x;
    const int wid = tid >> 5, lane = tid & 31;
    const int lr = lane >> 2, lq = lane & 3;
    const int warp_m = wid & 3, warp_n = wid >> 2;
    const int row0 = blockIdx.x * 128;
    const int col0 = blockIdx.y * 64;
    const int rA0 = warp_m * 32 + lr;
    const int rB0 = warp_n * 32 + lr;

    const int arow = tid >> 1, acol = (tid & 1) * 16;
    const int brow = tid >> 2, bcol = (tid & 3) * 8;
    int gar = row0 + arow; if (gar > N_NODES - 1) gar = N_NODES - 1;
    const float da = g_dinv[gar];
    const float* pA = g_ax + (size_t)gar * IN_DIM + acol;
    const float* pB = g_WcT + (size_t)(col0 + brow) * IN_DIM + bcol;

    float4 c00 = {0,0,0,0}, c01 = {0,0,0,0}, c02 = {0,0,0,0}, c03 = {0,0,0,0};
    float4 c10 = {0,0,0,0}, c11 = {0,0,0,0}, c12 = {0,0,0,0}, c13 = {0,0,0,0};

    float4 ra0 = *(const float4*)(pA + 0);
    float4 ra1 = *(const float4*)(pA + 4);
    float4 ra2 = *(const float4*)(pA + 8);
    float4 ra3 = *(const float4*)(pA + 12);
    float4 rb0 = *(const float4*)(pB + 0);
    float4 rb1 = *(const float4*)(pB + 4);

    #pragma unroll 1
    for (int c = 0; c < IN_DIM / 32; c++) {
        *(float4*)&As[arow][acol + 0]  = make_float4(ra0.x * da, ra0.y * da, ra0.z * da, ra0.w * da);
        *(float4*)&As[arow][acol + 4]  = make_float4(ra1.x * da, ra1.y * da, ra1.z * da, ra1.w * da);
        *(float4*)&As[arow][acol + 8]  = make_float4(ra2.x * da, ra2.y * da, ra2.z * da, ra2.w * da);
        *(float4*)&As[arow][acol + 12] = make_float4(ra3.x * da, ra3.y * da, ra3.z * da, ra3.w * da);
        *(float4*)&Bs[brow][bcol + 0] = rb0;
        *(float4*)&Bs[brow][bcol + 4] = rb1;
        __syncthreads();
        if (c + 1 < IN_DIM / 32) {
            const float* p_ = pA + (c + 1) * 32;
            ra0 = *(const float4*)(p_ + 0);
            ra1 = *(const float4*)(p_ + 4);
            ra2 = *(const float4*)(p_ + 8);
            ra3 = *(const float4*)(p_ + 12);
            const float* q_ = pB + (c + 1) * 32;
            rb0 = *(const float4*)(q_ + 0);
            rb1 = *(const float4*)(q_ + 4);
        }
        #pragma unroll
        for (int ks = 0; ks < 4; ks++) KSTEP();
        __syncthreads();
    }

    const int rbase = row0 + warp_m * 32 + lr;
    const int cbase = col0 + warp_n * 32 + 2 * lq;
    EPIW(ep1, c00, 0, 0, bias);  EPIW(ep1, c01, 0, 8, bias);
    EPIW(ep1, c02, 0, 16, bias); EPIW(ep1, c03, 0, 24, bias);
    EPIW(ep1, c10, 16, 0, bias); EPIW(ep1, c11, 16, 8, bias);
    EPIW(ep1, c12, 16, 16, bias); EPIW(ep1, c13, 16, 24, bias);
}

// -------- GEMM2: q = dinv .* (g_h2 @ W2T^T); q -> g_ax and out  [K=512] --------
__global__ __launch_bounds__(256) void k_gemm2(float* __restrict__ out) {
    __shared__ float As[128][ASTRIDE];
    __shared__ float Bs[64][ASTRIDE];
    const int tid = threadIdx.x;
    const int wid = tid >> 5, lane = tid & 31;
    const int lr = lane >> 2, lq = lane & 3;
    const int warp_m = wid & 3, warp_n = wid >> 2;
    const int row0 = blockIdx.x * 128;
    const int col0 = blockIdx.y * 64;
    const int rA0 = warp_m * 32 + lr;
    const int rB0 = warp_n * 32 + lr;

    const int arow = tid >> 1, acol = (tid & 1) * 16;
    const int brow = tid >> 2, bcol = (tid & 3) * 8;
    int gar = row0 + arow; if (gar > N_NODES - 1) gar = N_NODES - 1;
    const float* pA = g_h2 + (size_t)gar * HID + acol;
    const float* pB = g_W2T + (size_t)(col0 + brow) * HID + bcol;

    float4 c00 = {0,0,0,0}, c01 = {0,0,0,0}, c02 = {0,0,0,0}, c03 = {0,0,0,0};
    float4 c10 = {0,0,0,0}, c11 = {0,0,0,0}, c12 = {0,0,0,0}, c13 = {0,0,0,0};

    float4 ra0 = *(const float4*)(pA + 0);
    float4 ra1 = *(const float4*)(pA + 4);
    float4 ra2 = *(const float4*)(pA + 8);
    float4 ra3 = *(const float4*)(pA + 12);
    float4 rb0 = *(const float4*)(pB + 0);
    float4 rb1 = *(const float4*)(pB + 4);

    #pragma unroll 1
    for (int c = 0; c < HID / 32; c++) {
        *(float4*)&As[arow][acol + 0]  = ra0;
        *(float4*)&As[arow][acol + 4]  = ra1;
        *(float4*)&As[arow][acol + 8]  = ra2;
        *(float4*)&As[arow][acol + 12] = ra3;
        *(float4*)&Bs[brow][bcol + 0] = rb0;
        *(float4*)&Bs[brow][bcol + 4] = rb1;
        __syncthreads();
        if (c + 1 < HID / 32) {
            const float* p_ = pA + (c + 1) * 32;
            ra0 = *(const float4*)(p_ + 0);
            ra1 = *(const float4*)(p_ + 4);
            ra2 = *(const float4*)(p_ + 8);
            ra3 = *(const float4*)(p_ + 12);
            const float* q_ = pB + (c + 1) * 32;
            rb0 = *(const float4*)(q_ + 0);
            rb1 = *(const float4*)(q_ + 4);
        }
        #pragma unroll
        for (int ks = 0; ks < 4; ks++) KSTEP();
        __syncthreads();
    }

    const int rbase = row0 + warp_m * 32 + lr;
    const int cbase = col0 + warp_n * 32 + 2 * lq;
    EPIW(ep2, c00, 0, 0, out);  EPIW(ep2, c01, 0, 8, out);
    EPIW(ep2, c02, 0, 16, out); EPIW(ep2, c03, 0, 24, out);
    EPIW(ep2, c10, 16, 0, out); EPIW(ep2, c11, 16, 8, out);
    EPIW(ep2, c12, 16, 16, out); EPIW(ep2, c13, 16, 24, out);
}

// -------- scatter 2: out[dst] += q[src] --------
__global__ void k_scatter2(const void* __restrict__ ei, float* __restrict__ out) {
    int e = blockIdx.x * (blockDim.x >> 5) + (threadIdx.x >> 5);
    if (e >= E_EDGES) return;
    int lane = threadIdx.x & 31;
    int src = edge_at(ei, 0, e);
    int dst = edge_at(ei, 1, e);
    const float4* qs = (const float4*)(g_ax + (size_t)src * OUT_DIM);
    float* op = out + (size_t)dst * OUT_DIM;
    red_add4(op + lane * 4, qs[lane]);
    red_add4(op + (lane + 32) * 4, qs[lane + 32]);
}

// -------- final: out = sigmoid(dinv[v] * acc + b2) --------
__global__ void k_final(const float* __restrict__ b2, float* __restrict__ out) {
    int idx = blockIdx.x * blockDim.x + threadIdx.x;
    if (idx < N_NODES * (OUT_DIM / 4)) {
        int row = idx >> 6;
        float d = g_dinv[row];
        float4 v = ((float4*)out)[idx];
        float4 bv = ((const float4*)b2)[idx & 63];
        v.x = sigmoidf(d * v.x + bv.x);
        v.y = sigmoidf(d * v.y + bv.y);
        v.z = sigmoidf(d * v.z + bv.z);
        v.w = sigmoidf(d * v.w + bv.w);
        ((float4*)out)[idx] = v;
    }
}

// -------- launch --------
extern "C" void kernel_launch(void* const* d_in, const int* in_sizes, int n_in,
                              void* d_out, int out_size) {
    const float* x    = (const float*)d_in[0];
    const void*  ei   = d_in[1];
    const float* W_ae = (const float*)d_in[2];
    const float* b_ae = (const float*)d_in[3];
    const float* W1   = (const float*)d_in[4];
    const float* b1   = (const float*)d_in[5];
    const float* W2   = (const float*)d_in[6];
    const float* b2   = (const float*)d_in[7];
    float* out = (float*)d_out;

    k_detect<<<1, 32>>>((const int*)ei);
    k_init_deg<<<(N_NODES + 255) / 256, 256>>>();
    k_count<<<(E_EDGES + 255) / 256, 256>>>(ei);
    k_dinv<<<(N_NODES + 255) / 256, 256>>>();
    k_init_ax<<<(N_NODES * (IN_DIM / 4) + 255) / 256, 256>>>(x);
    k_scatter1<<<(E_EDGES + 7) / 8, 256>>>(ei, x);
    k_wc<<<dim3(2, 256), 256>>>(W_ae, W1);
    k_bb<<<2, 256>>>(b_ae, W1);
    k_wt2<<<(HID * OUT_DIM) / 256, 256>>>(W2);

    k_gemm1<<<dim3((N_NODES + 127) / 128, HID / 64), 256>>>(b1);
    k_gemm2<<<dim3((N_NODES + 127) / 128, OUT_DIM / 64), 256>>>(out);

    k_scatter2<<<(E_EDGES + 7) / 8, 256>>>(ei, out);
    k_final<<<(N_NODES * (OUT_DIM / 4) + 255) / 256, 256>>>(b2, out);
}

// round 16
// speedup vs baseline: 1.6771x; 1.4657x over previous
#include <cuda_runtime.h>
#include <cstdint>

// Problem constants (fixed by the dataset)
#define N_NODES 50000
#define E_EDGES 1600000
#define IN_DIM  256
#define HID     512
#define OUT_DIM 256
#define NBLK    ((N_NODES + 255) / 256)   // 196 scan blocks

// ---- GEMM tiling: 128x64 block, 8 warps, warp tile 32x32, K-chunk 32 fp32 ----
#define ASTRIDE 36   // smem row stride in floats (32 + 4 pad); 144B, 16B-aligned

// -------- scratch (module-static; no runtime allocation) --------
__device__ __align__(16) float g_dinv[N_NODES];
__device__ __align__(16) float g_t[N_NODES];
__device__ __align__(16) float g_ax[(size_t)N_NODES * IN_DIM];   // agg acc; reused as q after GEMM2
__device__ __align__(16) float g_h2[(size_t)N_NODES * HID];      // sigmoid(layer1), fp32
__device__ __align__(16) float g_WcT[(size_t)HID * IN_DIM];      // (W_ae@W1)^T [512][256]
__device__ __align__(16) float g_W2T[(size_t)OUT_DIM * HID];     // W2^T [256][512]
__device__ __align__(16) float g_bb[HID];                        // b_ae @ W1
__device__ int g_is64;
// CSR scratch
__device__ __align__(16) int g_degi[N_NODES];    // in-degree (excl self loop)
__device__ __align__(16) int g_exc[N_NODES];     // in-block exclusive prefix
__device__ __align__(16) int g_bsum[NBLK];       // per-block sums
__device__ __align__(16) int g_boff[NBLK];       // per-block exclusive offsets
__device__ __align__(16) int g_rowptr[N_NODES];  // CSR row start
__device__ __align__(16) int g_fill[N_NODES];    // atomic fill cursor
__device__ __align__(16) int g_csr[E_EDGES];     // src ids grouped by dst

// -------- helpers --------
__device__ __forceinline__ float sigmoidf(float z) { return 1.0f / (1.0f + __expf(-z)); }

// fp32 -> tf32 hi/lo split: hi = rna(v); lo = rna(v - hi). hi bits are a valid fp32.
#define CVT2(H, L, V) do { \
    asm("cvt.rna.tf32.f32 %0, %1;" : "=r"(H) : "f"(V)); \
    float r_ = (V) - __uint_as_float(H); \
    asm("cvt.rna.tf32.f32 %0, %1;" : "=r"(L) : "f"(r_)); } while (0)

// m16n8k8 tf32 MMA on a named float4 accumulator (scalar operands only).
#define MMAT(C, A0, A1, A2, A3, B0, B1) \
    asm volatile("mma.sync.aligned.m16n8k8.row.col.f32.tf32.tf32.f32 " \
        "{%0,%1,%2,%3}, {%4,%5,%6,%7}, {%8,%9}, {%0,%1,%2,%3};" \
        : "+f"((C).x), "+f"((C).y), "+f"((C).z), "+f"((C).w) \
        : "r"(A0), "r"(A1), "r"(A2), "r"(A3), "r"(B0), "r"(B1))

// Per-ks B fragment setup (8 loads, 16 cvts) then one DO_MT per m-subtile.
#define DO_MT(C0, C1, C2, C3, ROFF) do { \
    float va0_ = As[rA0 + (ROFF)][kq],     va1_ = As[rA0 + (ROFF) + 8][kq]; \
    float va2_ = As[rA0 + (ROFF)][kq4],    va3_ = As[rA0 + (ROFF) + 8][kq4]; \
    uint32_t ah0_, al0_, ah1_, al1_, ah2_, al2_, ah3_, al3_; \
    CVT2(ah0_, al0_, va0_); CVT2(ah1_, al1_, va1_); \
    CVT2(ah2_, al2_, va2_); CVT2(ah3_, al3_, va3_); \
    MMAT(C0, ah0_, ah1_, ah2_, ah3_, bh00, bh01); \
    MMAT(C0, ah0_, ah1_, ah2_, ah3_, bl00, bl01); \
    MMAT(C0, al0_, al1_, al2_, al3_, bh00, bh01); \
    MMAT(C1, ah0_, ah1_, ah2_, ah3_, bh10, bh11); \
    MMAT(C1, ah0_, ah1_, ah2_, ah3_, bl10, bl11); \
    MMAT(C1, al0_, al1_, al2_, al3_, bh10, bh11); \
    MMAT(C2, ah0_, ah1_, ah2_, ah3_, bh20, bh21); \
    MMAT(C2, ah0_, ah1_, ah2_, ah3_, bl20, bl21); \
    MMAT(C2, al0_, al1_, al2_, al3_, bh20, bh21); \
    MMAT(C3, ah0_, ah1_, ah2_, ah3_, bh30, bh31); \
    MMAT(C3, ah0_, ah1_, ah2_, ah3_, bl30, bl31); \
    MMAT(C3, al0_, al1_, al2_, al3_, bh30, bh31); } while (0)

#define KSTEP() do { \
    const int kq  = ks * 8 + lq; \
    const int kq4 = kq + 4; \
    uint32_t bh00, bl00, bh01, bl01, bh10, bl10, bh11, bl11; \
    uint32_t bh20, bl20, bh21, bl21, bh30, bl30, bh31, bl31; \
    { float v_; \
      v_ = Bs[rB0][kq];      CVT2(bh00, bl00, v_); \
      v_ = Bs[rB0][kq4];     CVT2(bh01, bl01, v_); \
      v_ = Bs[rB0 + 8][kq];  CVT2(bh10, bl10, v_); \
      v_ = Bs[rB0 + 8][kq4]; CVT2(bh11, bl11, v_); \
      v_ = Bs[rB0 + 16][kq]; CVT2(bh20, bl20, v_); \
      v_ = Bs[rB0 + 16][kq4];CVT2(bh21, bl21, v_); \
      v_ = Bs[rB0 + 24][kq]; CVT2(bh30, bl30, v_); \
      v_ = Bs[rB0 + 24][kq4];CVT2(bh31, bl31, v_); } \
    DO_MT(c00, c01, c02, c03, 0); \
    DO_MT(c10, c11, c12, c13, 16); } while (0)

// Read edge endpoint `which` (0=src, 1=dst) of edge e, dtype-agnostic.
__device__ __forceinline__ int edge_at(const void* ei, int which, int e) {
    if (g_is64) return (int)((const long long*)ei)[(size_t)which * E_EDGES + e];
    return ((const int*)ei)[(size_t)which * E_EDGES + e];
}

// -------- dtype detection --------
__global__ void k_detect(const int* __restrict__ ei32) {
    if (blockIdx.x == 0) {
        int is64 = 1;
        for (int i = 0; i < 1024; i++)
            if (ei32[2 * i + 1] != 0) { is64 = 0; break; }
        if (threadIdx.x == 0) g_is64 = is64;
    }
}

// -------- degree + dinv --------
__global__ void k_zero() {
    int i = blockIdx.x * blockDim.x + threadIdx.x;
    if (i < N_NODES) g_degi[i] = 0;
}
__global__ void k_count(const void* __restrict__ ei) {
    int e = blockIdx.x * blockDim.x + threadIdx.x;
    if (e < E_EDGES) atomicAdd(&g_degi[edge_at(ei, 1, e)], 1);
}
__global__ void k_dinv() {
    int i = blockIdx.x * blockDim.x + threadIdx.x;
    if (i < N_NODES) {
        float d = 1.0f + (float)g_degi[i];    // self loop + in-edges
        g_dinv[i] = rsqrtf(d);
    }
}

// -------- CSR build: block scan + aux scan + combine + fill --------
__global__ void k_scan1() {
    __shared__ int s[256];
    int i = blockIdx.x * 256 + threadIdx.x;
    int v = (i < N_NODES) ? g_degi[i] : 0;
    s[threadIdx.x] = v;
    __syncthreads();
    #pragma unroll
    for (int off = 1; off < 256; off <<= 1) {
        int t = (threadIdx.x >= off) ? s[threadIdx.x - off] : 0;
        __syncthreads();
        s[threadIdx.x] += t;
        __syncthreads();
    }
    if (i < N_NODES) g_exc[i] = s[threadIdx.x] - v;
    if (threadIdx.x == 255) g_bsum[blockIdx.x] = s[255];
}
__global__ void k_scan2() {
    __shared__ int s[256];
    int v = (threadIdx.x < NBLK) ? g_bsum[threadIdx.x] : 0;
    s[threadIdx.x] = v;
    __syncthreads();
    #pragma unroll
    for (int off = 1; off < 256; off <<= 1) {
        int t = (threadIdx.x >= off) ? s[threadIdx.x - off] : 0;
        __syncthreads();
        s[threadIdx.x] += t;
        __syncthreads();
    }
    if (threadIdx.x < NBLK) g_boff[threadIdx.x] = s[threadIdx.x] - v;
}
__global__ void k_scan3() {
    int i = blockIdx.x * 256 + threadIdx.x;
    if (i < N_NODES) {
        int r = g_exc[i] + g_boff[blockIdx.x];
        g_rowptr[i] = r;
        g_fill[i] = r;
    }
}
__global__ void k_fill(const void* __restrict__ ei) {
    int e = blockIdx.x * blockDim.x + threadIdx.x;
    if (e < E_EDGES) {
        int dst = edge_at(ei, 1, e);
        int pos = atomicAdd(&g_fill[dst], 1);
        g_csr[pos] = edge_at(ei, 0, e);
    }
}

// -------- gather 1: g_ax[v] = x[v]*dinv[v] + sum_src dinv[src]*x[src]; g_t[v] too --------
__global__ void k_gather1(const float* __restrict__ x) {
    int v = blockIdx.x * 8 + (threadIdx.x >> 5);
    if (v >= N_NODES) return;
    int lane = threadIdx.x & 31;
    int beg = g_rowptr[v];
    int end = beg + g_degi[v];
    float dv = g_dinv[v];
    const float4* xv = (const float4*)(x + (size_t)v * IN_DIM);
    float4 a0 = xv[lane];
    float4 a1 = xv[lane + 32];
    a0.x *= dv; a0.y *= dv; a0.z *= dv; a0.w *= dv;
    a1.x *= dv; a1.y *= dv; a1.z *= dv; a1.w *= dv;
    float t = dv;
    for (int e = beg; e < end; e++) {
        int src = g_csr[e];
        float w = g_dinv[src];
        const float4* xs = (const float4*)(x + (size_t)src * IN_DIM);
        float4 v0 = xs[lane];
        float4 v1 = xs[lane + 32];
        a0.x += w * v0.x; a0.y += w * v0.y; a0.z += w * v0.z; a0.w += w * v0.w;
        a1.x += w * v1.x; a1.y += w * v1.y; a1.z += w * v1.z; a1.w += w * v1.w;
        t += w;
    }
    float4* ax = (float4*)(g_ax + (size_t)v * IN_DIM);
    ax[lane] = a0;
    ax[lane + 32] = a1;
    if (lane == 0) g_t[v] = t;
}

// -------- gather 2: out[v] = q[v] + sum_src q[src]   (q in g_ax, 256-dim) --------
__global__ void k_gather2(float* __restrict__ out) {
    int v = blockIdx.x * 8 + (threadIdx.x >> 5);
    if (v >= N_NODES) return;
    int lane = threadIdx.x & 31;
    int beg = g_rowptr[v];
    int end = beg + g_degi[v];
    const float4* qv = (const float4*)(g_ax + (size_t)v * OUT_DIM);
    float4 a0 = qv[lane];
    float4 a1 = qv[lane + 32];
    for (int e = beg; e < end; e++) {
        int src = g_csr[e];
        const float4* qs = (const float4*)(g_ax + (size_t)src * OUT_DIM);
        float4 v0 = qs[lane];
        float4 v1 = qs[lane + 32];
        a0.x += v0.x; a0.y += v0.y; a0.z += v0.z; a0.w += v0.w;
        a1.x += v1.x; a1.y += v1.y; a1.z += v1.z; a1.w += v1.w;
    }
    float4* op = (float4*)(out + (size_t)v * OUT_DIM);
    op[lane] = a0;
    op[lane + 32] = a1;
}

// -------- weight prep (fp32) --------
// WcT[j][k] = (W_ae @ W1)[k][j]
__global__ void k_wc(const float* __restrict__ W_ae, const float* __restrict__ W1) {
    __shared__ float wa[HID];
    int k = blockIdx.y;                       // 0..255
    int j = blockIdx.x * 256 + threadIdx.x;   // 0..511
    for (int m = threadIdx.x; m < HID; m += 256) wa[m] = W_ae[k * HID + m];
    __syncthreads();
    float acc = 0.0f;
    #pragma unroll 8
    for (int m = 0; m < HID; m++) acc = fmaf(wa[m], W1[m * HID + j], acc);
    g_WcT[(size_t)j * IN_DIM + k] = acc;
}
__global__ void k_bb(const float* __restrict__ b_ae, const float* __restrict__ W1) {
    int j = blockIdx.x * 256 + threadIdx.x;
    if (j < HID) {
        float acc = 0.0f;
        for (int m = 0; m < HID; m++) acc = fmaf(b_ae[m], W1[m * HID + j], acc);
        g_bb[j] = acc;
    }
}
// W2T[j][k] = W2[k][j]
__global__ void k_wt2(const float* __restrict__ W2) {
    int idx = blockIdx.x * 256 + threadIdx.x;   // < 512*256
    int kk = idx >> 8;      // 0..511
    int j  = idx & 255;     // 0..255
    g_W2T[(size_t)j * HID + kk] = W2[kk * OUT_DIM + j];
}

// -------- epilogue helpers --------
__device__ __forceinline__ void ep1(float vx, float vy, int r, int col,
                                    const float* __restrict__ bias) {
    if (r < N_NODES) {
        float s1 = g_dinv[r] * g_t[r];
        float2 o = make_float2(sigmoidf(vx + s1 * g_bb[col] + bias[col]),
                               sigmoidf(vy + s1 * g_bb[col + 1] + bias[col + 1]));
        *(float2*)(g_h2 + (size_t)r * HID + col) = o;
    }
}
__device__ __forceinline__ void ep2(float vx, float vy, int r, int col,
                                    float* __restrict__ unused) {
    if (r < N_NODES) {
        float dv = g_dinv[r];
        *(float2*)(g_ax + (size_t)r * OUT_DIM + col) = make_float2(dv * vx, dv * vy);
    }
}

#define EPIW(EP, C, RO, CO, LAST) do { \
    EP((C).x, (C).y, rbase + (RO), cbase + (CO), LAST); \
    EP((C).z, (C).w, rbase + (RO) + 8, cbase + (CO), LAST); } while (0)

// -------- GEMM1: g_h2 = sigmoid(dinv.*(g_ax) @ WcT^T + s*bb + b1)  [K=256] --------
__global__ __launch_bounds__(256) void k_gemm1(const float* __restrict__ bias) {
    __shared__ float As[128][ASTRIDE];
    __shared__ float Bs[64][ASTRIDE];
    const int tid = threadIdx.x;
    const int wid = tid >> 5, lane = tid & 31;
    const int lr = lane >> 2, lq = lane & 3;
    const int warp_m = wid & 3, warp_n = wid >> 2;
    const int row0 = blockIdx.x * 128;
    const int col0 = blockIdx.y * 64;
    const int rA0 = warp_m * 32 + lr;
    const int rB0 = warp_n * 32 + lr;

    const int arow = tid >> 1, acol = (tid & 1) * 16;
    const int brow = tid >> 2, bcol = (tid & 3) * 8;
    int gar = row0 + arow; if (gar > N_NODES - 1) gar = N_NODES - 1;
    const float da = g_dinv[gar];
    const float* pA = g_ax + (size_t)gar * IN_DIM + acol;
    const float* pB = g_WcT + (size_t)(col0 + brow) * IN_DIM + bcol;

    float4 c00 = {0,0,0,0}, c01 = {0,0,0,0}, c02 = {0,0,0,0}, c03 = {0,0,0,0};
    float4 c10 = {0,0,0,0}, c11 = {0,0,0,0}, c12 = {0,0,0,0}, c13 = {0,0,0,0};

    float4 ra0 = *(const float4*)(pA + 0);
    float4 ra1 = *(const float4*)(pA + 4);
    float4 ra2 = *(const float4*)(pA + 8);
    float4 ra3 = *(const float4*)(pA + 12);
    float4 rb0 = *(const float4*)(pB + 0);
    float4 rb1 = *(const float4*)(pB + 4);

    #pragma unroll 1
    for (int c = 0; c < IN_DIM / 32; c++) {
        *(float4*)&As[arow][acol + 0]  = make_float4(ra0.x * da, ra0.y * da, ra0.z * da, ra0.w * da);
        *(float4*)&As[arow][acol + 4]  = make_float4(ra1.x * da, ra1.y * da, ra1.z * da, ra1.w * da);
        *(float4*)&As[arow][acol + 8]  = make_float4(ra2.x * da, ra2.y * da, ra2.z * da, ra2.w * da);
        *(float4*)&As[arow][acol + 12] = make_float4(ra3.x * da, ra3.y * da, ra3.z * da, ra3.w * da);
        *(float4*)&Bs[brow][bcol + 0] = rb0;
        *(float4*)&Bs[brow][bcol + 4] = rb1;
        __syncthreads();
        if (c + 1 < IN_DIM / 32) {
            const float* p_ = pA + (c + 1) * 32;
            ra0 = *(const float4*)(p_ + 0);
            ra1 = *(const float4*)(p_ + 4);
            ra2 = *(const float4*)(p_ + 8);
            ra3 = *(const float4*)(p_ + 12);
            const float* q_ = pB + (c + 1) * 32;
            rb0 = *(const float4*)(q_ + 0);
            rb1 = *(const float4*)(q_ + 4);
        }
        #pragma unroll
        for (int ks = 0; ks < 4; ks++) KSTEP();
        __syncthreads();
    }

    const int rbase = row0 + warp_m * 32 + lr;
    const int cbase = col0 + warp_n * 32 + 2 * lq;
    EPIW(ep1, c00, 0, 0, bias);  EPIW(ep1, c01, 0, 8, bias);
    EPIW(ep1, c02, 0, 16, bias); EPIW(ep1, c03, 0, 24, bias);
    EPIW(ep1, c10, 16, 0, bias); EPIW(ep1, c11, 16, 8, bias);
    EPIW(ep1, c12, 16, 16, bias); EPIW(ep1, c13, 16, 24, bias);
}

// -------- GEMM2: q = dinv .* (g_h2 @ W2T^T); q -> g_ax  [K=512] --------
__global__ __launch_bounds__(256) void k_gemm2() {
    __shared__ float As[128][ASTRIDE];
    __shared__ float Bs[64][ASTRIDE];
    const int tid = threadIdx.x;
    const int wid = tid >> 5, lane = tid & 31;
    const int lr = lane >> 2, lq = lane & 3;
    const int warp_m = wid & 3, warp_n = wid >> 2;
    const int row0 = blockIdx.x * 128;
    const int col0 = blockIdx.y * 64;
    const int rA0 = warp_m * 32 + lr;
    const int rB0 = warp_n * 32 + lr;

    const int arow = tid >> 1, acol = (tid & 1) * 16;
    const int brow = tid >> 2, bcol = (tid & 3) * 8;
    int gar = row0 + arow; if (gar > N_NODES - 1) gar = N_NODES - 1;
    const float* pA = g_h2 + (size_t)gar * HID + acol;
    const float* pB = g_W2T + (size_t)(col0 + brow) * HID + bcol;

    float4 c00 = {0,0,0,0}, c01 = {0,0,0,0}, c02 = {0,0,0,0}, c03 = {0,0,0,0};
    float4 c10 = {0,0,0,0}, c11 = {0,0,0,0}, c12 = {0,0,0,0}, c13 = {0,0,0,0};

    float4 ra0 = *(const float4*)(pA + 0);
    float4 ra1 = *(const float4*)(pA + 4);
    float4 ra2 = *(const float4*)(pA + 8);
    float4 ra3 = *(const float4*)(pA + 12);
    float4 rb0 = *(const float4*)(pB + 0);
    float4 rb1 = *(const float4*)(pB + 4);

    #pragma unroll 1
    for (int c = 0; c < HID / 32; c++) {
        *(float4*)&As[arow][acol + 0]  = ra0;
        *(float4*)&As[arow][acol + 4]  = ra1;
        *(float4*)&As[arow][acol + 8]  = ra2;
        *(float4*)&As[arow][acol + 12] = ra3;
        *(float4*)&Bs[brow][bcol + 0] = rb0;
        *(float4*)&Bs[brow][bcol + 4] = rb1;
        __syncthreads();
        if (c + 1 < HID / 32) {
            const float* p_ = pA + (c + 1) * 32;
            ra0 = *(const float4*)(p_ + 0);
            ra1 = *(const float4*)(p_ + 4);
            ra2 = *(const float4*)(p_ + 8);
            ra3 = *(const float4*)(p_ + 12);
            const float* q_ = pB + (c + 1) * 32;
            rb0 = *(const float4*)(q_ + 0);
            rb1 = *(const float4*)(q_ + 4);
        }
        #pragma unroll
        for (int ks = 0; ks < 4; ks++) KSTEP();
        __syncthreads();
    }

    const int rbase = row0 + warp_m * 32 + lr;
    const int cbase = col0 + warp_n * 32 + 2 * lq;
    EPIW(ep2, c00, 0, 0, nullptr);  EPIW(ep2, c01, 0, 8, nullptr);
    EPIW(ep2, c02, 0, 16, nullptr); EPIW(ep2, c03, 0, 24, nullptr);
    EPIW(ep2, c10, 16, 0, nullptr); EPIW(ep2, c11, 16, 8, nullptr);
    EPIW(ep2, c12, 16, 16, nullptr); EPIW(ep2, c13, 16, 24, nullptr);
}

// -------- final: out = sigmoid(dinv[v] * acc + b2) --------
__global__ void k_final(const float* __restrict__ b2, float* __restrict__ out) {
    int idx = blockIdx.x * blockDim.x + threadIdx.x;
    if (idx < N_NODES * (OUT_DIM / 4)) {
        int row = idx >> 6;
        float d = g_dinv[row];
        float4 v = ((float4*)out)[idx];
        float4 bv = ((const float4*)b2)[idx & 63];
        v.x = sigmoidf(d * v.x + bv.x);
        v.y = sigmoidf(d * v.y + bv.y);
        v.z = sigmoidf(d * v.z + bv.z);
        v.w = sigmoidf(d * v.w + bv.w);
        ((float4*)out)[idx] = v;
    }
}

// -------- launch --------
extern "C" void kernel_launch(void* const* d_in, const int* in_sizes, int n_in,
                              void* d_out, int out_size) {
    const float* x    = (const float*)d_in[0];
    const void*  ei   = d_in[1];
    const float* W_ae = (const float*)d_in[2];
    const float* b_ae = (const float*)d_in[3];
    const float* W1   = (const float*)d_in[4];
    const float* b1   = (const float*)d_in[5];
    const float* W2   = (const float*)d_in[6];
    const float* b2   = (const float*)d_in[7];
    float* out = (float*)d_out;

    k_detect<<<1, 32>>>((const int*)ei);
    k_zero<<<NBLK, 256>>>();
    k_count<<<(E_EDGES + 255) / 256, 256>>>(ei);
    k_dinv<<<NBLK, 256>>>();
    k_scan1<<<NBLK, 256>>>();
    k_scan2<<<1, 256>>>();
    k_scan3<<<NBLK, 256>>>();
    k_fill<<<(E_EDGES + 255) / 256, 256>>>(ei);
    k_gather1<<<(N_NODES + 7) / 8, 256>>>(x);
    k_wc<<<dim3(2, 256), 256>>>(W_ae, W1);
    k_bb<<<2, 256>>>(b_ae, W1);
    k_wt2<<<(HID * OUT_DIM) / 256, 256>>>(W2);

    k_gemm1<<<dim3((N_NODES + 127) / 128, HID / 64), 256>>>(b1);
    k_gemm2<<<dim3((N_NODES + 127) / 128, OUT_DIM / 64), 256>>>();

    k_gather2<<<(N_NODES + 7) / 8, 256>>>(out);
    k_final<<<(N_NODES * (OUT_DIM / 4) + 255) / 256, 256>>>(b2, out);
}